// round 9
// baseline (speedup 1.0000x reference)
#include <cuda_runtime.h>
#include <cuda_fp16.h>
#include <cstdint>
#include <cstddef>

// R9: 512 threads / 16 warps (4M x 4N), B fragments via ldmatrix from a
// persistent 48KB smem weight tile. Doubles independent MMA chains per SMSP
// (8 -> 16) to discriminate latency-bound vs rate-bound legacy HMMA.
// Keeps R8: f16-accumulate MMA + fp32 promote every 4 ks, MUFU tanh epilogue,
// split arrive/wait group barrier. 128 CTAs = 8 M-groups x 16 N-tiles.

#define SEQ   512
#define BATCH 512
#define DIM   128
#define HID   256
#define G4    1024
#define NCTA  128
#define NTHR  512
#define NKS   24             // K = 384 = 24 x 16
#define NGRP  16             // CTAs per barrier group (one M tile)

#define SA_BYTES  49152      // A tile: 24 ks x 2048B (64 rows x 16 k fp16)
#define SB_BYTES  49152      // B tile: 24 ks x 2048B (4 wN x 4 mats x 128B)
#define SMEM_TOTAL (SA_BYTES + SB_BYTES)

// ---- persistent device scratch ----
__device__ __align__(16) __half g_h16[2][BATCH * HID];
__device__ __align__(128) unsigned long long g_bar_grp[8][16]; // 128B apart

__device__ __forceinline__ uint32_t smem_u32(const void* p) {
    uint32_t a;
    asm("{ .reg .u64 t; cvta.to.shared.u64 t, %1; cvt.u32.u64 %0, t; }"
        : "=r"(a) : "l"(p));
    return a;
}
__device__ __forceinline__ void ldsm4(uint32_t a[4], uint32_t addr) {
    asm volatile("ldmatrix.sync.aligned.m8n8.x4.shared.b16 {%0,%1,%2,%3}, [%4];"
                 : "=r"(a[0]), "=r"(a[1]), "=r"(a[2]), "=r"(a[3]) : "r"(addr));
}
// f16-accumulate MMA: D(f16x2 in 2 regs) = A*B + D
__device__ __forceinline__ void mma_f16acc(uint32_t c[2], const uint32_t a[4],
                                           uint32_t b0, uint32_t b1) {
    asm volatile(
        "mma.sync.aligned.m16n8k16.row.col.f16.f16.f16.f16 "
        "{%0,%1}, {%2,%3,%4,%5}, {%6,%7}, {%0,%1};"
        : "+r"(c[0]), "+r"(c[1])
        : "r"(a[0]), "r"(a[1]), "r"(a[2]), "r"(a[3]), "r"(b0), "r"(b1));
}
__device__ __forceinline__ void promote(float acc[4], uint32_t hc[2]) {
    float2 lo = __half22float2(*reinterpret_cast<__half2*>(&hc[0]));
    float2 hi = __half22float2(*reinterpret_cast<__half2*>(&hc[1]));
    acc[0] += lo.x; acc[1] += lo.y; acc[2] += hi.x; acc[3] += hi.y;
    hc[0] = 0u; hc[1] = 0u;
}

__device__ __forceinline__ float tanh_mufu(float x) {
    float y;
    asm("tanh.approx.f32 %0, %1;" : "=f"(y) : "f"(x));
    return y;
}
__device__ __forceinline__ float sig_mufu(float x) {
    return fmaf(0.5f, tanh_mufu(0.5f * x), 0.5f);
}

// A-tile swizzled offset: block per kstep = 64 rows x 32B.
__device__ __forceinline__ uint32_t a_phys(int ks, int row, int kh /*0,1*/) {
    return (uint32_t)(ks * 2048 + row * 32 + ((kh << 4) ^ ((row & 4) << 2)));
}

__global__ void __launch_bounds__(NTHR, 1)
lstm_hmma(const float* __restrict__ x,  const float* __restrict__ Wx,
          const float* __restrict__ Wh, const float* __restrict__ bv,
          const float* __restrict__ Wd, const float* __restrict__ bd,
          float* __restrict__ out)
{
    extern __shared__ __align__(1024) char smem[];
    char* sA = smem;                 // 48 KB A tile
    char* sB = smem + SA_BYTES;      // 48 KB persistent weights
    const uint32_t sA_u = smem_u32(sA);
    const uint32_t sB_u = sA_u + SA_BYTES;

    const int tid  = threadIdx.x;
    const int cta  = blockIdx.x;
    const int warp = tid >> 5, lane = tid & 31;
    const int grp = cta >> 4;           // M-tile group (16 CTAs)
    const int r0 = grp * 64;            // 64 batch rows
    const int j0 = (cta & 15) * 16;     // 16 hidden cols
    const int wM = warp & 3;            // 4-way M split (16 rows)
    const int wN = warp >> 2;           // 4-way N split (16 n-cols)
    unsigned long long* const bar_ctr = &g_bar_grp[grp][0];

    // ---- one-time: weight slice fp32->fp16 into sB ----
    // n = 4*jl + gate; per ks per wN: 4 mats [nb][khalf] of 8x8 b16 (128B).
    for (int idx = tid; idx < 384 * 64; idx += NTHR) {
        int k = idx >> 6, n = idx & 63;
        int col = (n & 3) * HID + j0 + (n >> 2);
        float w = (k < DIM) ? Wx[(size_t)k * G4 + col]
                            : Wh[(size_t)(k - DIM) * G4 + col];
        int ks = k >> 4, kl = k & 15, wNi = n >> 4, nl = n & 15;
        int mat = ((nl >> 3) << 1) | (kl >> 3);
        int off = ks * 2048 + wNi * 512 + mat * 128 + (nl & 7) * 16 + (kl & 7) * 2;
        *(__half*)(sB + off) = __float2half_rn(w);
    }

    // zero h buffer 0 (65536 threads x 4B = 256KB)
    ((uint32_t*)g_h16[0])[cta * NTHR + tid] = 0u;

    // epilogue geometry: q = lane&3; even lane handles row r, odd row r+8.
    const int q = lane & 3;
    const int myOdd = lane & 1;
    const int rowE = wM * 16 + (lane >> 2) + (myOdd ? 8 : 0);
    float bI[2], bF[2], bG[2], bO[2];
    #pragma unroll
    for (int nb = 0; nb < 2; ++nb) {
        int j = j0 + wN * 4 + nb * 2 + (q >> 1);
        bI[nb] = bv[j];
        bF[nb] = bv[HID + j];
        bG[nb] = bv[2 * HID + j];
        bO[nb] = bv[3 * HID + j];
    }
    float cst[2] = {0.f, 0.f};

    // loader coords: 512 threads; x: 16 halfs/thread, h: 32 halfs/thread
    const int srow = tid >> 3;            // 0..63
    const int xkb  = (tid & 7) * 16;      // x k-base (16 floats)
    const int hkb  = (tid & 7) * 32;      // h k-base (32 halfs)

    // ldmatrix addresses
    uint32_t ldsA = sA_u + a_phys(0, wM * 16 + (lane & 15), lane >> 4);
    uint32_t ldsB = sB_u + wN * 512 + (lane >> 3) * 128 + (lane & 7) * 16;

    // ---- prologue: stage x(0) ----
    {
        const float* xp = x + ((size_t)(r0 + srow) * SEQ + 0) * DIM + xkb;
        #pragma unroll
        for (int c2 = 0; c2 < 2; ++c2) {
            float4 v0 = *(const float4*)(xp + c2 * 8);
            float4 v1 = *(const float4*)(xp + c2 * 8 + 4);
            union { __half2 h; uint32_t u; } q0, q1, q2, q3;
            q0.h = __floats2half2_rn(v0.x, v0.y);
            q1.h = __floats2half2_rn(v0.z, v0.w);
            q2.h = __floats2half2_rn(v1.x, v1.y);
            q3.h = __floats2half2_rn(v1.z, v1.w);
            int k = xkb + c2 * 8;
            *(uint4*)(sA + a_phys(k >> 4, srow, (k >> 3) & 1)) =
                make_uint4(q0.u, q1.u, q2.u, q3.u);
        }
    }

    // full barrier once (h0 + x(0) + sB visible)
    {
        __syncthreads();
        if (tid == 0) {
            __threadfence();
            unsigned long long t = atomicAdd(bar_ctr, 1ULL) + 1ULL;
            unsigned long long target =
                ((t + (unsigned long long)NGRP - 1ULL) / NGRP) *
                (unsigned long long)NGRP;
            unsigned long long v;
            do {
                asm volatile("ld.acquire.gpu.u64 %0, [%1];"
                             : "=l"(v) : "l"(bar_ctr) : "memory");
            } while (v < target);
        }
        __syncthreads();
    }

    for (int s = 0; s < SEQ; ++s) {
        // -- issue h(s) loads first (L1-bypass); hide under x-part MMAs
        const __half* hp = g_h16[s & 1];
        const uint4* hsrc = (const uint4*)(hp + (size_t)(r0 + srow) * HID + hkb);
        uint4 hr[4];
        #pragma unroll
        for (int c = 0; c < 4; ++c) hr[c] = __ldcv(hsrc + c);

        float acc[2][4];
        uint32_t hc[2][2];
        #pragma unroll
        for (int nb = 0; nb < 2; ++nb) {
            #pragma unroll
            for (int k = 0; k < 4; ++k) acc[nb][k] = 0.f;
            hc[nb][0] = 0u; hc[nb][1] = 0u;
        }

        // -- x-part MMAs (ks 0..7), promote every 4
        #pragma unroll
        for (int g4 = 0; g4 < 2; ++g4) {
            #pragma unroll
            for (int kq = 0; kq < 4; ++kq) {
                int ks = g4 * 4 + kq;
                uint32_t am[4], bm[4];
                ldsm4(am, ldsA + ks * 2048);
                ldsm4(bm, ldsB + ks * 2048);
                mma_f16acc(hc[0], am, bm[0], bm[1]);
                mma_f16acc(hc[1], am, bm[2], bm[3]);
            }
            promote(acc[0], hc[0]); promote(acc[1], hc[1]);
        }

        // -- stage h into sA
        #pragma unroll
        for (int c = 0; c < 4; ++c) {
            int kg = DIM + hkb + c * 8;
            *(uint4*)(sA + a_phys(kg >> 4, srow, (kg >> 3) & 1)) = hr[c];
        }
        __syncthreads();

        // -- h-part MMAs (ks 8..23), promote every 4
        #pragma unroll
        for (int g4 = 0; g4 < 4; ++g4) {
            #pragma unroll
            for (int kq = 0; kq < 4; ++kq) {
                int ks = 8 + g4 * 4 + kq;
                uint32_t am[4], bm[4];
                ldsm4(am, ldsA + ks * 2048);
                ldsm4(bm, ldsB + ks * 2048);
                mma_f16acc(hc[0], am, bm[0], bm[1]);
                mma_f16acc(hc[1], am, bm[2], bm[3]);
            }
            promote(acc[0], hc[0]); promote(acc[1], hc[1]);
        }

        // -- gate exchange across lane pairs (q even holds i,f; q odd g,o)
        float sx[2][4];
        #pragma unroll
        for (int nb = 0; nb < 2; ++nb)
            #pragma unroll
            for (int k = 0; k < 4; ++k)
                sx[nb][k] = __shfl_xor_sync(0xffffffffu, acc[nb][k], 1);

        __half* hn = g_h16[(s + 1) & 1];
        #pragma unroll
        for (int nb = 0; nb < 2; ++nb) {
            float zi = myOdd ? sx[nb][2] : acc[nb][0];
            float zf = myOdd ? sx[nb][3] : acc[nb][1];
            float zg = myOdd ? acc[nb][2] : sx[nb][0];
            float zo = myOdd ? acc[nb][3] : sx[nb][1];
            float iv = sig_mufu(zi + bI[nb]);
            float fv = sig_mufu(zf + bF[nb]);
            float gv = tanh_mufu(zg + bG[nb]);
            float ov = sig_mufu(zo + bO[nb]);
            cst[nb] = fv * cst[nb] + iv * gv;
            int j = j0 + wN * 4 + nb * 2 + (q >> 1);
            hn[(size_t)(r0 + rowE) * HID + j] =
                __float2half_rn(ov * tanh_mufu(cst[nb]));
        }

        // -- split barrier: arrive (release), stage x(s+1) in the window
        __syncthreads();                      // h stores + sA reads done
        unsigned long long tick = 0;
        if (tid == 0) {
            asm volatile("atom.add.release.gpu.global.u64 %0, [%1], 1;"
                         : "=l"(tick) : "l"(bar_ctr) : "memory");
            tick += 1ULL;
        }
        if (s + 1 < SEQ) {
            const float* xp = x + ((size_t)(r0 + srow) * SEQ + (s + 1)) * DIM + xkb;
            #pragma unroll
            for (int c2 = 0; c2 < 2; ++c2) {
                float4 v0 = *(const float4*)(xp + c2 * 8);
                float4 v1 = *(const float4*)(xp + c2 * 8 + 4);
                union { __half2 h; uint32_t u; } q0, q1, q2, q3;
                q0.h = __floats2half2_rn(v0.x, v0.y);
                q1.h = __floats2half2_rn(v0.z, v0.w);
                q2.h = __floats2half2_rn(v1.x, v1.y);
                q3.h = __floats2half2_rn(v1.z, v1.w);
                int k = xkb + c2 * 8;
                *(uint4*)(sA + a_phys(k >> 4, srow, (k >> 3) & 1)) =
                    make_uint4(q0.u, q1.u, q2.u, q3.u);
            }
        }
        if (tid == 0) {
            unsigned long long target =
                ((tick + (unsigned long long)NGRP - 1ULL) / NGRP) *
                (unsigned long long)NGRP;
            unsigned long long v;
            do {
                asm volatile("ld.acquire.gpu.u64 %0, [%1];"
                             : "=l"(v) : "l"(bar_ctr) : "memory");
            } while (v < target);
        }
        __syncthreads();
    }

    // ---- classifier + softmax: 128 CTAs x 4 warps = 512 rows ----
    if (warp < 4) {
        const int row = cta * 4 + warp;
        const __half* hf = g_h16[0];
        float acc10[10];
        #pragma unroll
        for (int c = 0; c < 10; ++c) acc10[c] = 0.f;
        uint4 hv = __ldcv((const uint4*)(hf + (size_t)row * HID + lane * 8));
        const __half* hvh = (const __half*)&hv;
        #pragma unroll
        for (int u = 0; u < 8; ++u) {
            float h = __half2float(hvh[u]);
            const float* wd = Wd + (size_t)(lane * 8 + u) * 10;
            #pragma unroll
            for (int c = 0; c < 10; ++c) acc10[c] += h * wd[c];
        }
        #pragma unroll
        for (int off = 16; off > 0; off >>= 1) {
            #pragma unroll
            for (int c = 0; c < 10; ++c)
                acc10[c] += __shfl_down_sync(0xffffffffu, acc10[c], off);
        }
        if (lane == 0) {
            float m = -3.0e38f;
            #pragma unroll
            for (int c = 0; c < 10; ++c) { acc10[c] += bd[c]; m = fmaxf(m, acc10[c]); }
            float ssum = 0.f;
            #pragma unroll
            for (int c = 0; c < 10; ++c) { acc10[c] = __expf(acc10[c] - m); ssum += acc10[c]; }
            float inv = 1.0f / ssum;
            #pragma unroll
            for (int c = 0; c < 10; ++c) out[(size_t)row * 10 + c] = acc10[c] * inv;
        }
    }
}

extern "C" void kernel_launch(void* const* d_in, const int* in_sizes, int n_in,
                              void* d_out, int out_size) {
    const float* x  = (const float*)d_in[0];
    const float* Wx = (const float*)d_in[1];
    const float* Wh = (const float*)d_in[2];
    const float* b  = (const float*)d_in[3];
    const float* Wd = (const float*)d_in[4];
    const float* bd = (const float*)d_in[5];
    (void)in_sizes; (void)n_in; (void)out_size;
    cudaFuncSetAttribute(lstm_hmma, cudaFuncAttributeMaxDynamicSharedMemorySize,
                         SMEM_TOTAL);
    lstm_hmma<<<NCTA, NTHR, SMEM_TOTAL>>>(x, Wx, Wh, b, Wd, bd, (float*)d_out);
}